// round 1
// baseline (speedup 1.0000x reference)
#include <cuda_runtime.h>
#include <cuda_bf16.h>
#include <math.h>

// ---------------- problem constants ----------------
#define Bb   4
#define Ll   2048
#define Dd   1024
#define Ee   8
#define Kk   2
#define FFf  4096
#define F_TOT (Bb*Ll)            // 8192
#define CAP   2560               // int(8192*2/8*1.25)

// ---------------- scratch (device globals; no allocation) ----------------
__device__ int   g_topi [F_TOT * Kk];
__device__ float g_gate [F_TOT * Kk];
__device__ int   g_pos  [F_TOT * Kk];     // capacity position per (token,k), -1 if dropped
__device__ int   g_disp [Ee * CAP];       // token id per (expert, slot)
__device__ int   g_count[Ee];
__device__ float g_xin  [Ee * CAP * Dd];     // 80 MB
__device__ float g_h    [(size_t)Ee * CAP * FFf]; // 320 MB
__device__ float g_out2 [Ee * CAP * Dd];     // 80 MB

// ---------------- 1. gating: one warp per token ----------------
__global__ void gating_kernel(const float* __restrict__ x,
                              const float* __restrict__ noise,
                              const float* __restrict__ Wg, const float* __restrict__ bg,
                              const float* __restrict__ Wn, const float* __restrict__ bn)
{
    int warp = (blockIdx.x * blockDim.x + threadIdx.x) >> 5;
    int lane = threadIdx.x & 31;
    if (warp >= F_TOT) return;
    const float* xr = x + (size_t)warp * Dd;

    float ag[Ee], an[Ee];
#pragma unroll
    for (int e = 0; e < Ee; e++) { ag[e] = 0.f; an[e] = 0.f; }

    for (int d = lane; d < Dd; d += 32) {
        float xv = xr[d];
#pragma unroll
        for (int e = 0; e < Ee; e++) {
            ag[e] = fmaf(xv, Wg[d * Ee + e], ag[e]);
            an[e] = fmaf(xv, Wn[d * Ee + e], an[e]);
        }
    }
#pragma unroll
    for (int off = 16; off > 0; off >>= 1) {
#pragma unroll
        for (int e = 0; e < Ee; e++) {
            ag[e] += __shfl_down_sync(0xffffffffu, ag[e], off);
            an[e] += __shfl_down_sync(0xffffffffu, an[e], off);
        }
    }
    if (lane == 0) {
        float noisy[Ee];
#pragma unroll
        for (int e = 0; e < Ee; e++) {
            float l  = ag[e] + bg[e];
            float nl = an[e] + bn[e];
            // softplus = max(x,0) + log1p(exp(-|x|))  (stable, matches jax)
            float sp = fmaxf(nl, 0.f) + log1pf(expf(-fabsf(nl)));
            noisy[e] = l + noise[(size_t)warp * Ee + e] * sp;
        }
        int i0 = 0;
#pragma unroll
        for (int e = 1; e < Ee; e++) if (noisy[e] > noisy[i0]) i0 = e;
        int i1 = -1;
#pragma unroll
        for (int e = 0; e < Ee; e++) {
            if (e == i0) continue;
            if (i1 < 0 || noisy[e] > noisy[i1]) i1 = e;
        }
        float z  = expf(noisy[i1] - noisy[i0]);   // <= 1
        float g0 = 1.f / (1.f + z);
        float g1 = z * g0;
        g_topi[warp * 2 + 0] = i0;
        g_topi[warp * 2 + 1] = i1;
        g_gate[warp * 2 + 0] = g0;
        g_gate[warp * 2 + 1] = g1;
    }
}

// ---------------- 2. per-expert token-order scan ----------------
__global__ void scan_kernel()
{
    const int e   = blockIdx.x;     // 8 blocks
    const int tid = threadIdx.x;    // 256 threads
    __shared__ int sdata[256];
    __shared__ int sbase;
    if (tid == 0) sbase = 0;
    __syncthreads();

    for (int start = 0; start < F_TOT; start += 256) {
        int t  = start + tid;
        int i0 = g_topi[t * 2 + 0];
        int i1 = g_topi[t * 2 + 1];
        int m  = (i0 == e || i1 == e) ? 1 : 0;
        sdata[tid] = m;
        __syncthreads();
        // Hillis-Steele inclusive scan over 256
#pragma unroll
        for (int off = 1; off < 256; off <<= 1) {
            int v = (tid >= off) ? sdata[tid - off] : 0;
            __syncthreads();
            sdata[tid] += v;
            __syncthreads();
        }
        int incl = sdata[tid];
        int p = sbase + incl - 1;
        if (m) {
            int k = (i0 == e) ? 0 : 1;
            if (p < CAP) {
                g_disp[e * CAP + p] = t;
                g_pos[t * 2 + k] = p;
            } else {
                g_pos[t * 2 + k] = -1;
            }
        }
        __syncthreads();
        if (tid == 0) sbase += sdata[255];
        __syncthreads();
    }
    if (tid == 0) g_count[e] = min(sbase, CAP);
}

// ---------------- 3. gather xin rows ----------------
__global__ void gather_kernel(const float* __restrict__ x)
{
    int e = blockIdx.x / CAP;
    int c = blockIdx.x % CAP;
    if (c >= g_count[e]) return;
    int t = g_disp[e * CAP + c];
    const float4* src = (const float4*)(x + (size_t)t * Dd);
    float4* dst = (float4*)(g_xin + ((size_t)e * CAP + c) * Dd);
    dst[threadIdx.x] = src[threadIdx.x];   // 256 threads * float4 = 1024 floats
}

// ---------------- 4/5. SGEMM (128x128x8 tile, 8x8 micro) ----------------
// C[e] (M x N) = A[e] (M x Kd) @ B[e] (Kd x N) + bias[e]; optional exact GELU.
__global__ void __launch_bounds__(256, 2)
sgemm_kernel(const float* __restrict__ Aall, const float* __restrict__ Ball,
             const float* __restrict__ biasAll, float* __restrict__ Call,
             int M, int N, int Kd, int applyGelu)
{
    const int BM = 128, BN = 128, BK = 8, TM = 8, TN = 8;
    int e = blockIdx.z;
    if ((int)blockIdx.y * BM >= g_count[e]) return;

    const float* A    = Aall   + (size_t)e * M * Kd;
    const float* B    = Ball   + (size_t)e * Kd * N;
    const float* bias = biasAll + (size_t)e * N;
    float*       C    = Call   + (size_t)e * M * N;

    __shared__ float As[BK][BM];
    __shared__ float Bs[BK][BN];

    int tid  = threadIdx.x;
    int aRow = tid >> 1;            // 0..127
    int aCol = (tid & 1) * 4;       // 0 or 4
    int bRow = tid >> 5;            // 0..7
    int bCol = (tid & 31) * 4;      // 0..124
    int tRow = (tid >> 4) * TM;     // 0..120
    int tCol = (tid & 15) * TN;     // 0..120

    float acc[TM][TN];
#pragma unroll
    for (int i = 0; i < TM; i++)
#pragma unroll
        for (int j = 0; j < TN; j++) acc[i][j] = 0.f;

    const float* Aptr = A + (size_t)(blockIdx.y * BM + aRow) * Kd + aCol;
    const float* Bptr = B + (size_t)bRow * N + blockIdx.x * BN + bCol;

    for (int k0 = 0; k0 < Kd; k0 += BK) {
        float4 a4 = *(const float4*)Aptr;
        As[aCol + 0][aRow] = a4.x;
        As[aCol + 1][aRow] = a4.y;
        As[aCol + 2][aRow] = a4.z;
        As[aCol + 3][aRow] = a4.w;
        float4 b4 = *(const float4*)Bptr;
        *(float4*)&Bs[bRow][bCol] = b4;
        __syncthreads();
        Aptr += BK;
        Bptr += (size_t)BK * N;

        float regM[TM], regN[TN];
#pragma unroll
        for (int k = 0; k < BK; k++) {
#pragma unroll
            for (int i = 0; i < TM; i++) regM[i] = As[k][tRow + i];
#pragma unroll
            for (int j = 0; j < TN; j++) regN[j] = Bs[k][tCol + j];
#pragma unroll
            for (int i = 0; i < TM; i++)
#pragma unroll
                for (int j = 0; j < TN; j++)
                    acc[i][j] = fmaf(regM[i], regN[j], acc[i][j]);
        }
        __syncthreads();
    }

    int cBase = blockIdx.x * BN + tCol;
#pragma unroll
    for (int i = 0; i < TM; i++) {
        float* crow = C + (size_t)(blockIdx.y * BM + tRow + i) * N + cBase;
#pragma unroll
        for (int j = 0; j < TN; j += 4) {
            float4 v;
            float* pv = (float*)&v;
#pragma unroll
            for (int q = 0; q < 4; q++) {
                float t = acc[i][j + q] + bias[cBase + j + q];
                if (applyGelu)
                    t = 0.5f * t * (1.f + erff(t * 0.70710678118654752f));
                pv[q] = t;
            }
            *(float4*)(crow + j) = v;
        }
    }
}

// ---------------- 6. deterministic combine ----------------
__global__ void combine_kernel(float* __restrict__ out)
{
    int t = blockIdx.x;              // 8192 blocks
    int i0 = g_topi[t * 2 + 0], i1 = g_topi[t * 2 + 1];
    int p0 = g_pos [t * 2 + 0], p1 = g_pos [t * 2 + 1];
    float gv0 = g_gate[t * 2 + 0], gv1 = g_gate[t * 2 + 1];

    float4 acc = make_float4(0.f, 0.f, 0.f, 0.f);
    int d4 = threadIdx.x;            // 256 threads * float4 = 1024
    if (p0 >= 0) {
        float4 a = ((const float4*)(g_out2 + ((size_t)i0 * CAP + p0) * Dd))[d4];
        acc.x += gv0 * a.x; acc.y += gv0 * a.y; acc.z += gv0 * a.z; acc.w += gv0 * a.w;
    }
    if (p1 >= 0) {
        float4 b = ((const float4*)(g_out2 + ((size_t)i1 * CAP + p1) * Dd))[d4];
        acc.x += gv1 * b.x; acc.y += gv1 * b.y; acc.z += gv1 * b.z; acc.w += gv1 * b.w;
    }
    ((float4*)(out + (size_t)t * Dd))[d4] = acc;
}

// ---------------- launch ----------------
extern "C" void kernel_launch(void* const* d_in, const int* in_sizes, int n_in,
                              void* d_out, int out_size)
{
    const float* x     = (const float*)d_in[0];
    const float* noise = (const float*)d_in[1];
    const float* Wg    = (const float*)d_in[2];
    const float* bg    = (const float*)d_in[3];
    const float* Wn    = (const float*)d_in[4];
    const float* bn    = (const float*)d_in[5];
    const float* W1    = (const float*)d_in[6];
    const float* b1    = (const float*)d_in[7];
    const float* W2    = (const float*)d_in[8];
    const float* b2    = (const float*)d_in[9];
    float* out = (float*)d_out;

    // 1. gating: 8 warps/block -> 1024 blocks
    gating_kernel<<<F_TOT / 8, 256>>>(x, noise, Wg, bg, Wn, bn);
    // 2. scan
    scan_kernel<<<Ee, 256>>>();
    // 3. gather
    gather_kernel<<<Ee * CAP, 256>>>(x);

    float* xin  = nullptr; float* h = nullptr; float* out2 = nullptr;
    cudaGetSymbolAddress((void**)&xin,  g_xin);
    cudaGetSymbolAddress((void**)&h,    g_h);
    cudaGetSymbolAddress((void**)&out2, g_out2);

    // 4. GEMM1 + GELU: M=CAP(2560), N=FF(4096), K=D(1024)
    {
        dim3 grid(FFf / 128, CAP / 128, Ee);
        sgemm_kernel<<<grid, 256>>>(xin, W1, b1, h, CAP, FFf, Dd, 1);
    }
    // 5. GEMM2: M=CAP, N=D(1024), K=FF(4096)
    {
        dim3 grid(Dd / 128, CAP / 128, Ee);
        sgemm_kernel<<<grid, 256>>>(h, W2, b2, out2, CAP, Dd, FFf, 0);
    }
    // 6. combine
    combine_kernel<<<F_TOT, 256>>>(out);
}

// round 3
// speedup vs baseline: 4.8444x; 4.8444x over previous
#include <cuda_runtime.h>
#include <cuda_bf16.h>
#include <math.h>
#include <stdint.h>

// ---------------- problem constants ----------------
#define Bb   4
#define Ll   2048
#define Dd   1024
#define Ee   8
#define FFf  4096
#define F_TOT (Bb*Ll)            // 8192
#define CAP   2560               // int(8192*2/8*1.25)

// Does this compilation pass have sm_103a-specific features (tcgen05)?
#if defined(__CUDA_ARCH_FEAT_SM103_ALL) || defined(__CUDA_ARCH_SPECIFIC__)
#define HAS_TCGEN05 1
#else
#define HAS_TCGEN05 0
#endif

// ---------------- scratch (device globals; no allocation) ----------------
__device__ int   g_topi [F_TOT * 2];
__device__ float g_gate [F_TOT * 2];
__device__ int   g_pos  [F_TOT * 2];
__device__ int   g_disp [Ee * CAP];
__device__ int   g_count[Ee];
__device__ __nv_bfloat16 g_xin_h[(size_t)Ee * CAP * Dd];
__device__ __nv_bfloat16 g_xin_l[(size_t)Ee * CAP * Dd];
__device__ __nv_bfloat16 g_w1t_h[(size_t)Ee * FFf * Dd];
__device__ __nv_bfloat16 g_w1t_l[(size_t)Ee * FFf * Dd];
__device__ __nv_bfloat16 g_w2t_h[(size_t)Ee * Dd * FFf];
__device__ __nv_bfloat16 g_w2t_l[(size_t)Ee * Dd * FFf];
__device__ __nv_bfloat16 g_h_h  [(size_t)Ee * CAP * FFf];
__device__ __nv_bfloat16 g_h_l  [(size_t)Ee * CAP * FFf];
__device__ float         g_out2 [(size_t)Ee * CAP * Dd];

// ---------------- PTX helpers (arch-neutral) ----------------
__device__ __forceinline__ uint32_t smem_u32(const void* p) {
    uint32_t a;
    asm("{ .reg .u64 t; cvta.to.shared.u64 t, %1; cvt.u32.u64 %0, t; }" : "=r"(a) : "l"(p));
    return a;
}
#define CP_COMMIT() asm volatile("cp.async.commit_group;" ::: "memory")
#define SW128(o) ((o) ^ ((((uint32_t)(o)) >> 3) & 0x70))

// ---------------- 1. gating ----------------
__global__ void gating_kernel(const float* __restrict__ x,
                              const float* __restrict__ noise,
                              const float* __restrict__ Wg, const float* __restrict__ bg,
                              const float* __restrict__ Wn, const float* __restrict__ bn)
{
    int warp = (blockIdx.x * blockDim.x + threadIdx.x) >> 5;
    int lane = threadIdx.x & 31;
    if (warp >= F_TOT) return;
    const float* xr = x + (size_t)warp * Dd;
    float ag[Ee], an[Ee];
#pragma unroll
    for (int e = 0; e < Ee; e++) { ag[e] = 0.f; an[e] = 0.f; }
    for (int d = lane; d < Dd; d += 32) {
        float xv = xr[d];
#pragma unroll
        for (int e = 0; e < Ee; e++) {
            ag[e] = fmaf(xv, Wg[d * Ee + e], ag[e]);
            an[e] = fmaf(xv, Wn[d * Ee + e], an[e]);
        }
    }
#pragma unroll
    for (int off = 16; off > 0; off >>= 1)
#pragma unroll
        for (int e = 0; e < Ee; e++) {
            ag[e] += __shfl_down_sync(0xffffffffu, ag[e], off);
            an[e] += __shfl_down_sync(0xffffffffu, an[e], off);
        }
    if (lane == 0) {
        float noisy[Ee];
#pragma unroll
        for (int e = 0; e < Ee; e++) {
            float l  = ag[e] + bg[e];
            float nl = an[e] + bn[e];
            float sp = fmaxf(nl, 0.f) + log1pf(expf(-fabsf(nl)));
            noisy[e] = l + noise[(size_t)warp * Ee + e] * sp;
        }
        int i0 = 0;
#pragma unroll
        for (int e = 1; e < Ee; e++) if (noisy[e] > noisy[i0]) i0 = e;
        int i1 = -1;
#pragma unroll
        for (int e = 0; e < Ee; e++) {
            if (e == i0) continue;
            if (i1 < 0 || noisy[e] > noisy[i1]) i1 = e;
        }
        float z = expf(noisy[i1] - noisy[i0]);
        float g0 = 1.f / (1.f + z);
        g_topi[warp * 2 + 0] = i0;
        g_topi[warp * 2 + 1] = i1;
        g_gate[warp * 2 + 0] = g0;
        g_gate[warp * 2 + 1] = z * g0;
    }
}

// ---------------- 2. per-expert token-order scan ----------------
__global__ void scan_kernel()
{
    const int e = blockIdx.x;
    const int tid = threadIdx.x;
    __shared__ int sdata[256];
    __shared__ int sbase;
    if (tid == 0) sbase = 0;
    __syncthreads();
    for (int start = 0; start < F_TOT; start += 256) {
        int t = start + tid;
        int i0 = g_topi[t * 2 + 0];
        int i1 = g_topi[t * 2 + 1];
        int m = (i0 == e || i1 == e) ? 1 : 0;
        sdata[tid] = m;
        __syncthreads();
#pragma unroll
        for (int off = 1; off < 256; off <<= 1) {
            int v = (tid >= off) ? sdata[tid - off] : 0;
            __syncthreads();
            sdata[tid] += v;
            __syncthreads();
        }
        int p = sbase + sdata[tid] - 1;
        if (m) {
            int k = (i0 == e) ? 0 : 1;
            if (p < CAP) { g_disp[e * CAP + p] = t; g_pos[t * 2 + k] = p; }
            else         { g_pos[t * 2 + k] = -1; }
        }
        __syncthreads();
        if (tid == 0) sbase += sdata[255];
        __syncthreads();
    }
    if (tid == 0) g_count[e] = min(sbase, CAP);
}

// ---------------- 3. gather + bf16 split ----------------
__global__ void gather_split_kernel(const float* __restrict__ x)
{
    int e = blockIdx.x / CAP;
    int c = blockIdx.x % CAP;
    size_t base = ((size_t)e * CAP + c) * Dd + threadIdx.x * 4;
    if (c < g_count[e]) {
        int t = g_disp[e * CAP + c];
        float4 v = ((const float4*)(x + (size_t)t * Dd))[threadIdx.x];
        float vv[4] = {v.x, v.y, v.z, v.w};
#pragma unroll
        for (int q = 0; q < 4; q += 2) {
            __nv_bfloat16 h0 = __float2bfloat16(vv[q]);
            __nv_bfloat16 h1 = __float2bfloat16(vv[q + 1]);
            __nv_bfloat16 l0 = __float2bfloat16(vv[q] - __bfloat162float(h0));
            __nv_bfloat16 l1 = __float2bfloat16(vv[q + 1] - __bfloat162float(h1));
            *(__nv_bfloat162*)(g_xin_h + base + q) = __halves2bfloat162(h0, h1);
            *(__nv_bfloat162*)(g_xin_l + base + q) = __halves2bfloat162(l0, l1);
        }
    } else {
        __nv_bfloat162 z = __halves2bfloat162(__float2bfloat16(0.f), __float2bfloat16(0.f));
#pragma unroll
        for (int q = 0; q < 4; q += 2) {
            *(__nv_bfloat162*)(g_xin_h + base + q) = z;
            *(__nv_bfloat162*)(g_xin_l + base + q) = z;
        }
    }
}

// ---------------- 4. weight transpose + split ----------------
__global__ void transpose_split_kernel(const float* __restrict__ W,
                                       __nv_bfloat16* __restrict__ Th,
                                       __nv_bfloat16* __restrict__ Tl,
                                       int R, int C)
{
    __shared__ float tile[32][33];
    int e = blockIdx.z;
    const float* We = W + (size_t)e * R * C;
    int c = blockIdx.x * 32 + threadIdx.x;
#pragma unroll
    for (int j = 0; j < 4; j++) {
        int r = blockIdx.y * 32 + threadIdx.y + j * 8;
        tile[threadIdx.y + j * 8][threadIdx.x] = We[(size_t)r * C + c];
    }
    __syncthreads();
    int r2 = blockIdx.y * 32 + threadIdx.x;
    size_t ebase = (size_t)e * C * R;
#pragma unroll
    for (int j = 0; j < 4; j++) {
        int c2 = blockIdx.x * 32 + threadIdx.y + j * 8;
        float v = tile[threadIdx.x][threadIdx.y + j * 8];
        __nv_bfloat16 h = __float2bfloat16(v);
        __nv_bfloat16 l = __float2bfloat16(v - __bfloat162float(h));
        Th[ebase + (size_t)c2 * R + r2] = h;
        Tl[ebase + (size_t)c2 * R + r2] = l;
    }
}

// ---------------- 5. GEMM: tile 128x128, BK=64, split-bf16 (hh+hl+lh) ----------------
// smem layout: [0] tmem ptr, [16/24] mbars, [1024 + s*65536): Ah(16K) Al(16K) Bh(16K) Bl(16K)
__device__ __forceinline__ void stage_load(uint32_t stoff,
    const __nv_bfloat16* Ah, const __nv_bfloat16* Al,
    const __nv_bfloat16* Bh, const __nv_bfloat16* Bl,
    int m0, int n0, int K, int k0, int tid)
{
#pragma unroll
    for (int i = 0; i < 16; i++) {
        int c = i * 256 + tid;            // 0..4095 16B chunks
        int tsel = c >> 10;               // 0 Ah, 1 Al, 2 Bh, 3 Bl
        int cc = c & 1023;
        int row = cc >> 3, kc = cc & 7;
        const __nv_bfloat16* T = (tsel == 0) ? Ah : (tsel == 1) ? Al : (tsel == 2) ? Bh : Bl;
        int r0 = (tsel < 2) ? m0 : n0;
        const __nv_bfloat16* src = T + (size_t)(r0 + row) * K + k0 + kc * 8;
        uint32_t dst = stoff + (uint32_t)tsel * 16384u + SW128(row * 128 + kc * 16);
        asm volatile("cp.async.cg.shared.global [%0], [%1], 16;" :: "r"(dst), "l"(src));
    }
}

__global__ void __launch_bounds__(256, 1)
moe_gemm_kernel(const __nv_bfloat16* __restrict__ Ah, const __nv_bfloat16* __restrict__ Al,
                const __nv_bfloat16* __restrict__ Bh, const __nv_bfloat16* __restrict__ Bl,
                const float* __restrict__ bias,
                __nv_bfloat16* __restrict__ outH, __nv_bfloat16* __restrict__ outL,
                float* __restrict__ outF,
                int K, int Ntot, int mode)
{
    extern __shared__ __align__(1024) char smem[];
    int e = blockIdx.z;
    int m0 = blockIdx.y * 128;
    if (m0 >= g_count[e]) return;
    int n0 = blockIdx.x * 128;
    int tid = threadIdx.x;
    int wid = tid >> 5, lid = tid & 31;

    const __nv_bfloat16* eAh = Ah + (size_t)e * CAP * K;
    const __nv_bfloat16* eAl = Al + (size_t)e * CAP * K;
    const __nv_bfloat16* eBh = Bh + (size_t)e * Ntot * K;
    const __nv_bfloat16* eBl = Bl + (size_t)e * Ntot * K;
    const float* ebias = bias + (size_t)e * Ntot;

    uint32_t sb = smem_u32(smem);
    const int S = K >> 6;

    // prefetch 2 stages
    stage_load(sb + 1024, eAh, eAl, eBh, eBl, m0, n0, K, 0, tid);
    CP_COMMIT();
    stage_load(sb + 1024 + 65536, eAh, eAl, eBh, eBl, m0, n0, K, 64, tid);
    CP_COMMIT();

#if HAS_TCGEN05
    // ================= tcgen05 path =================
    uint32_t mbar0 = sb + 16, mbar1 = sb + 24;
    if (tid == 0) {
        asm volatile("mbarrier.init.shared.b64 [%0], 1;" :: "r"(mbar0) : "memory");
        asm volatile("mbarrier.init.shared.b64 [%0], 1;" :: "r"(mbar1) : "memory");
    }
    if (wid == 0)
        asm volatile("tcgen05.alloc.cta_group::1.sync.aligned.shared::cta.b32 [%0], 128;"
                     :: "r"(sb) : "memory");
    __syncthreads();
    uint32_t tmem;
    asm volatile("ld.shared.b32 %0, [%1];" : "=r"(tmem) : "r"(sb));

    const uint32_t IDESC = (8u << 24) | (16u << 17) | (1u << 10) | (1u << 7) | (1u << 4);
    int ph0 = 0, ph1 = 0;
    for (int s = 0; s < S; s++) {
        if (s < S - 1) asm volatile("cp.async.wait_group 1;" ::: "memory");
        else           asm volatile("cp.async.wait_group 0;" ::: "memory");
        asm volatile("fence.proxy.async.shared::cta;" ::: "memory");
        __syncthreads();
        uint32_t stoff = sb + 1024 + (uint32_t)(s & 1) * 65536u;
        uint32_t pred;
        asm volatile("{ .reg .pred p; elect.sync _|p, 0xFFFFFFFF; selp.b32 %0, 1, 0, p; }" : "=r"(pred));
        if (wid == 0 && pred) {
            uint64_t base = ((uint64_t)2 << 61) | ((uint64_t)1 << 46) | ((uint64_t)64 << 32) | ((uint64_t)1 << 16);
            uint64_t dAh = base | ((stoff >> 4) & 0x3FFF);
            uint64_t dAl = base | (((stoff + 16384u) >> 4) & 0x3FFF);
            uint64_t dBh = base | (((stoff + 32768u) >> 4) & 0x3FFF);
            uint64_t dBl = base | (((stoff + 49152u) >> 4) & 0x3FFF);
#pragma unroll
            for (int kc = 0; kc < 4; kc++) {
                uint32_t en = (s | kc) != 0;
                asm volatile("{ .reg .pred p; setp.ne.u32 p, %4, 0;\n\t"
                    "tcgen05.mma.cta_group::1.kind::f16 [%0], %1, %2, %3, {%5,%5,%5,%5}, p; }"
                    :: "r"(tmem), "l"(dAh + kc * 2), "l"(dBh + kc * 2), "r"(IDESC), "r"(en), "r"(0u) : "memory");
            }
#pragma unroll
            for (int kc = 0; kc < 4; kc++)
                asm volatile("{ .reg .pred p; setp.ne.u32 p, 1, 0;\n\t"
                    "tcgen05.mma.cta_group::1.kind::f16 [%0], %1, %2, %3, {%4,%4,%4,%4}, p; }"
                    :: "r"(tmem), "l"(dAh + kc * 2), "l"(dBl + kc * 2), "r"(IDESC), "r"(0u) : "memory");
#pragma unroll
            for (int kc = 0; kc < 4; kc++)
                asm volatile("{ .reg .pred p; setp.ne.u32 p, 1, 0;\n\t"
                    "tcgen05.mma.cta_group::1.kind::f16 [%0], %1, %2, %3, {%4,%4,%4,%4}, p; }"
                    :: "r"(tmem), "l"(dAl + kc * 2), "l"(dBh + kc * 2), "r"(IDESC), "r"(0u) : "memory");
            asm volatile("tcgen05.commit.cta_group::1.mbarrier::arrive::one.shared::cluster.b64 [%0];"
                         :: "r"((s & 1) ? mbar1 : mbar0) : "memory");
        }
        if (s + 2 < S) {
            uint32_t mb = (s & 1) ? mbar1 : mbar0;
            uint32_t pp = (s & 1) ? ph1 : ph0;
            asm volatile("{ .reg .pred P1;\n\t"
                "WL_%=:\n\t"
                "mbarrier.try_wait.parity.acquire.cta.shared::cta.b64 P1, [%0], %1, 0x989680;\n\t"
                "@P1 bra.uni WD_%=;\n\tbra.uni WL_%=;\n\tWD_%=:\n\t}"
                :: "r"(mb), "r"(pp) : "memory");
            if (s & 1) ph1 ^= 1; else ph0 ^= 1;
            stage_load(sb + 1024 + (uint32_t)(s & 1) * 65536u,
                       eAh, eAl, eBh, eBl, m0, n0, K, (s + 2) * 64, tid);
            CP_COMMIT();
        }
    }
    {
        uint32_t mb = ((S - 1) & 1) ? mbar1 : mbar0;
        uint32_t pp = ((S - 1) & 1) ? ph1 : ph0;
        asm volatile("{ .reg .pred P1;\n\t"
            "WL_%=:\n\t"
            "mbarrier.try_wait.parity.acquire.cta.shared::cta.b64 P1, [%0], %1, 0x989680;\n\t"
            "@P1 bra.uni WD_%=;\n\tbra.uni WL_%=;\n\tWD_%=:\n\t}"
            :: "r"(mb), "r"(pp) : "memory");
    }
    asm volatile("tcgen05.fence::after_thread_sync;" ::: "memory");

    if (wid < 4) {
        uint32_t woff = (uint32_t)wid << 21;
        int m = m0 + wid * 32 + lid;
#pragma unroll 1
        for (int ch = 0; ch < 4; ch++) {
            uint32_t r[32];
            asm volatile("tcgen05.ld.sync.aligned.32x32b.x32.b32 "
                "{%0, %1, %2, %3, %4, %5, %6, %7, "
                " %8, %9, %10, %11, %12, %13, %14, %15, "
                " %16, %17, %18, %19, %20, %21, %22, %23, "
                " %24, %25, %26, %27, %28, %29, %30, %31}, [%32];"
                : "=r"(r[0]), "=r"(r[1]), "=r"(r[2]), "=r"(r[3]),
                  "=r"(r[4]), "=r"(r[5]), "=r"(r[6]), "=r"(r[7]),
                  "=r"(r[8]), "=r"(r[9]), "=r"(r[10]), "=r"(r[11]),
                  "=r"(r[12]), "=r"(r[13]), "=r"(r[14]), "=r"(r[15]),
                  "=r"(r[16]), "=r"(r[17]), "=r"(r[18]), "=r"(r[19]),
                  "=r"(r[20]), "=r"(r[21]), "=r"(r[22]), "=r"(r[23]),
                  "=r"(r[24]), "=r"(r[25]), "=r"(r[26]), "=r"(r[27]),
                  "=r"(r[28]), "=r"(r[29]), "=r"(r[30]), "=r"(r[31])
                : "r"(tmem + woff + ch * 32));
            asm volatile("tcgen05.wait::ld.sync.aligned;" ::: "memory");
            int nbase = n0 + ch * 32;
            if (mode == 1) {
                __nv_bfloat16* ph_ = outH + ((size_t)e * CAP + m) * Ntot + nbase;
                __nv_bfloat16* pl_ = outL + ((size_t)e * CAP + m) * Ntot + nbase;
#pragma unroll
                for (int j = 0; j < 32; j += 2) {
                    float v0 = __uint_as_float(r[j])     + ebias[nbase + j];
                    float v1 = __uint_as_float(r[j + 1]) + ebias[nbase + j + 1];
                    v0 = 0.5f * v0 * (1.f + erff(v0 * 0.70710678118654752f));
                    v1 = 0.5f * v1 * (1.f + erff(v1 * 0.70710678118654752f));
                    __nv_bfloat16 h0 = __float2bfloat16(v0);
                    __nv_bfloat16 h1 = __float2bfloat16(v1);
                    __nv_bfloat16 l0 = __float2bfloat16(v0 - __bfloat162float(h0));
                    __nv_bfloat16 l1 = __float2bfloat16(v1 - __bfloat162float(h1));
                    *(__nv_bfloat162*)(ph_ + j) = __halves2bfloat162(h0, h1);
                    *(__nv_bfloat162*)(pl_ + j) = __halves2bfloat162(l0, l1);
                }
            } else {
                float* po = outF + ((size_t)e * CAP + m) * Ntot + nbase;
#pragma unroll
                for (int j = 0; j < 32; j += 4) {
                    float4 v;
                    v.x = __uint_as_float(r[j])     + ebias[nbase + j];
                    v.y = __uint_as_float(r[j + 1]) + ebias[nbase + j + 1];
                    v.z = __uint_as_float(r[j + 2]) + ebias[nbase + j + 2];
                    v.w = __uint_as_float(r[j + 3]) + ebias[nbase + j + 3];
                    *(float4*)(po + j) = v;
                }
            }
        }
    }
    __syncthreads();
    if (wid == 0) {
        asm volatile("tcgen05.relinquish_alloc_permit.cta_group::1.sync.aligned;");
        asm volatile("tcgen05.dealloc.cta_group::1.sync.aligned.b32 %0, 128;" :: "r"(tmem));
    }
#else
    // ================= mma.sync bf16 fallback (plain sm_103) =================
    #define LDSM_X4(r0_, r1_, r2_, r3_, addr_)                                   \
        asm volatile("ldmatrix.sync.aligned.m8n8.x4.shared.b16 {%0,%1,%2,%3}, [%4];" \
            : "=r"(r0_), "=r"(r1_), "=r"(r2_), "=r"(r3_) : "r"(addr_))
    #define MMA16816(d_, a_, b_)                                                 \
        asm volatile("mma.sync.aligned.m16n8k16.row.col.f32.bf16.bf16.f32 "      \
            "{%0,%1,%2,%3}, {%4,%5,%6,%7}, {%8,%9}, {%0,%1,%2,%3};"              \
            : "+f"((d_)[0]), "+f"((d_)[1]), "+f"((d_)[2]), "+f"((d_)[3])          \
            : "r"((a_)[0]), "r"((a_)[1]), "r"((a_)[2]), "r"((a_)[3]),             \
              "r"((b_)[0]), "r"((b_)[1]))

    int wm = wid & 3;       // M quadrant (32 rows)
    int wn = wid >> 2;      // N half (64 cols)
    float acc[2][8][4];
#pragma unroll
    for (int mi = 0; mi < 2; mi++)
#pragma unroll
        for (int nt = 0; nt < 8; nt++)
#pragma unroll
            for (int q = 0; q < 4; q++) acc[mi][nt][q] = 0.f;

    int ar  = wm * 32;
    int bnb = wn * 64;
    uint32_t a_lrow = (uint32_t)(lid & 15);
    uint32_t a_lk   = (uint32_t)((lid >> 4) * 16);

    for (int s = 0; s < S; s++) {
        if (s < S - 1) asm volatile("cp.async.wait_group 1;" ::: "memory");
        else           asm volatile("cp.async.wait_group 0;" ::: "memory");
        __syncthreads();
        uint32_t so = sb + 1024 + (uint32_t)(s & 1) * 65536u;
        uint32_t aoffH = so, aoffL = so + 16384u, boffH = so + 32768u, boffL = so + 49152u;
#pragma unroll
        for (int ks = 0; ks < 4; ks++) {
            uint32_t kb = (uint32_t)ks * 32u + a_lk;
            uint32_t ah[2][4], al[2][4], bh[8][2], bl[8][2];
#pragma unroll
            for (int mi = 0; mi < 2; mi++) {
                uint32_t off = SW128((ar + mi * 16 + a_lrow) * 128u + kb);
                LDSM_X4(ah[mi][0], ah[mi][1], ah[mi][2], ah[mi][3], aoffH + off);
                LDSM_X4(al[mi][0], al[mi][1], al[mi][2], al[mi][3], aoffL + off);
            }
#pragma unroll
            for (int p = 0; p < 4; p++) {
                uint32_t off = SW128((bnb + p * 16 + a_lrow) * 128u + kb);
                uint32_t r0, r1, r2, r3;
                LDSM_X4(r0, r1, r2, r3, boffH + off);
                bh[2*p][0] = r0; bh[2*p][1] = r2; bh[2*p+1][0] = r1; bh[2*p+1][1] = r3;
                LDSM_X4(r0, r1, r2, r3, boffL + off);
                bl[2*p][0] = r0; bl[2*p][1] = r2; bl[2*p+1][0] = r1; bl[2*p+1][1] = r3;
            }
#pragma unroll
            for (int mi = 0; mi < 2; mi++)
#pragma unroll
                for (int nt = 0; nt < 8; nt++) {
                    MMA16816(acc[mi][nt], ah[mi], bh[nt]);
                    MMA16816(acc[mi][nt], ah[mi], bl[nt]);
                    MMA16816(acc[mi][nt], al[mi], bh[nt]);
                }
        }
        __syncthreads();
        if (s + 2 < S) {
            stage_load(sb + 1024 + (uint32_t)(s & 1) * 65536u,
                       eAh, eAl, eBh, eBl, m0, n0, K, (s + 2) * 64, tid);
            CP_COMMIT();
        }
    }

    // epilogue
#pragma unroll
    for (int mi = 0; mi < 2; mi++)
#pragma unroll
        for (int nt = 0; nt < 8; nt++) {
            int col = n0 + wn * 64 + nt * 8 + (lid & 3) * 2;
#pragma unroll
            for (int half = 0; half < 2; half++) {
                int row = m0 + wm * 32 + mi * 16 + (lid >> 2) + half * 8;
                float v0 = acc[mi][nt][half * 2 + 0] + ebias[col];
                float v1 = acc[mi][nt][half * 2 + 1] + ebias[col + 1];
                if (mode == 1) {
                    v0 = 0.5f * v0 * (1.f + erff(v0 * 0.70710678118654752f));
                    v1 = 0.5f * v1 * (1.f + erff(v1 * 0.70710678118654752f));
                    __nv_bfloat16 h0 = __float2bfloat16(v0);
                    __nv_bfloat16 h1 = __float2bfloat16(v1);
                    __nv_bfloat16 l0 = __float2bfloat16(v0 - __bfloat162float(h0));
                    __nv_bfloat16 l1 = __float2bfloat16(v1 - __bfloat162float(h1));
                    size_t o = ((size_t)e * CAP + row) * Ntot + col;
                    *(__nv_bfloat162*)(outH + o) = __halves2bfloat162(h0, h1);
                    *(__nv_bfloat162*)(outL + o) = __halves2bfloat162(l0, l1);
                } else {
                    float2 v; v.x = v0; v.y = v1;
                    *(float2*)(outF + ((size_t)e * CAP + row) * Ntot + col) = v;
                }
            }
        }
#endif
}

// ---------------- 6. deterministic combine ----------------
__global__ void combine_kernel(float* __restrict__ out)
{
    int t = blockIdx.x;
    int i0 = g_topi[t * 2 + 0], i1 = g_topi[t * 2 + 1];
    int p0 = g_pos [t * 2 + 0], p1 = g_pos [t * 2 + 1];
    float gv0 = g_gate[t * 2 + 0], gv1 = g_gate[t * 2 + 1];
    float4 acc = make_float4(0.f, 0.f, 0.f, 0.f);
    int d4 = threadIdx.x;
    if (p0 >= 0) {
        float4 a = ((const float4*)(g_out2 + ((size_t)i0 * CAP + p0) * Dd))[d4];
        acc.x += gv0 * a.x; acc.y += gv0 * a.y; acc.z += gv0 * a.z; acc.w += gv0 * a.w;
    }
    if (p1 >= 0) {
        float4 b = ((const float4*)(g_out2 + ((size_t)i1 * CAP + p1) * Dd))[d4];
        acc.x += gv1 * b.x; acc.y += gv1 * b.y; acc.z += gv1 * b.z; acc.w += gv1 * b.w;
    }
    ((float4*)(out + (size_t)t * Dd))[d4] = acc;
}

// ---------------- launch ----------------
extern "C" void kernel_launch(void* const* d_in, const int* in_sizes, int n_in,
                              void* d_out, int out_size)
{
    const float* x     = (const float*)d_in[0];
    const float* noise = (const float*)d_in[1];
    const float* Wg    = (const float*)d_in[2];
    const float* bg    = (const float*)d_in[3];
    const float* Wn    = (const float*)d_in[4];
    const float* bn    = (const float*)d_in[5];
    const float* W1    = (const float*)d_in[6];
    const float* b1    = (const float*)d_in[7];
    const float* W2    = (const float*)d_in[8];
    const float* b2    = (const float*)d_in[9];
    float* out = (float*)d_out;

    cudaFuncSetAttribute(moe_gemm_kernel,
                         cudaFuncAttributeMaxDynamicSharedMemorySize, 132096);

    __nv_bfloat16 *xin_h, *xin_l, *w1t_h, *w1t_l, *w2t_h, *w2t_l, *h_h, *h_l;
    float* out2;
    cudaGetSymbolAddress((void**)&xin_h, g_xin_h);
    cudaGetSymbolAddress((void**)&xin_l, g_xin_l);
    cudaGetSymbolAddress((void**)&w1t_h, g_w1t_h);
    cudaGetSymbolAddress((void**)&w1t_l, g_w1t_l);
    cudaGetSymbolAddress((void**)&w2t_h, g_w2t_h);
    cudaGetSymbolAddress((void**)&w2t_l, g_w2t_l);
    cudaGetSymbolAddress((void**)&h_h, g_h_h);
    cudaGetSymbolAddress((void**)&h_l, g_h_l);
    cudaGetSymbolAddress((void**)&out2, g_out2);

    gating_kernel<<<F_TOT / 8, 256>>>(x, noise, Wg, bg, Wn, bn);
    scan_kernel<<<Ee, 256>>>();
    gather_split_kernel<<<Ee * CAP, 256>>>(x);
    transpose_split_kernel<<<dim3(FFf / 32, Dd / 32, Ee), dim3(32, 8)>>>(W1, w1t_h, w1t_l, Dd, FFf);
    transpose_split_kernel<<<dim3(Dd / 32, FFf / 32, Ee), dim3(32, 8)>>>(W2, w2t_h, w2t_l, FFf, Dd);

    // GEMM1: M=CAP, N=FF, K=D; bias b1; GELU; split-bf16 output
    moe_gemm_kernel<<<dim3(FFf / 128, CAP / 128, Ee), 256, 132096>>>(
        xin_h, xin_l, w1t_h, w1t_l, b1, h_h, h_l, nullptr, Dd, FFf, 1);
    // GEMM2: M=CAP, N=D, K=FF; bias b2; fp32 output
    moe_gemm_kernel<<<dim3(Dd / 128, CAP / 128, Ee), 256, 132096>>>(
        h_h, h_l, w2t_h, w2t_l, b2, nullptr, nullptr, out2, FFf, Dd, 0);

    combine_kernel<<<F_TOT, 256>>>(out);
}

// round 4
// speedup vs baseline: 5.1909x; 1.0715x over previous
#include <cuda_runtime.h>
#include <cuda_bf16.h>
#include <math.h>
#include <stdint.h>

// ---------------- problem constants ----------------
#define Bb   4
#define Ll   2048
#define Dd   1024
#define Ee   8
#define FFf  4096
#define F_TOT (Bb*Ll)            // 8192
#define CAP   2560               // int(8192*2/8*1.25)

// Does this compilation pass have sm_103a-specific features (tcgen05)?
#if defined(__CUDA_ARCH_FEAT_SM103_ALL) || defined(__CUDA_ARCH_SPECIFIC__)
#define HAS_TCGEN05 1
#else
#define HAS_TCGEN05 0
#endif

// ---------------- scratch (device globals; no allocation) ----------------
__device__ int   g_topi [F_TOT * 2];
__device__ float g_gate [F_TOT * 2];
__device__ int   g_pos  [F_TOT * 2];
__device__ int   g_disp [Ee * CAP];
__device__ int   g_count[Ee];
__device__ __nv_bfloat16 g_xin_h[(size_t)Ee * CAP * Dd];
__device__ __nv_bfloat16 g_xin_l[(size_t)Ee * CAP * Dd];
__device__ __nv_bfloat16 g_w1t_h[(size_t)Ee * FFf * Dd];
__device__ __nv_bfloat16 g_w1t_l[(size_t)Ee * FFf * Dd];
__device__ __nv_bfloat16 g_w2t_h[(size_t)Ee * Dd * FFf];
__device__ __nv_bfloat16 g_w2t_l[(size_t)Ee * Dd * FFf];
__device__ __nv_bfloat16 g_h_h  [(size_t)Ee * CAP * FFf];
__device__ __nv_bfloat16 g_h_l  [(size_t)Ee * CAP * FFf];
__device__ float         g_out2 [(size_t)Ee * CAP * Dd];

// ---------------- PTX helpers (arch-neutral) ----------------
__device__ __forceinline__ uint32_t smem_u32(const void* p) {
    uint32_t a;
    asm("{ .reg .u64 t; cvta.to.shared.u64 t, %1; cvt.u32.u64 %0, t; }" : "=r"(a) : "l"(p));
    return a;
}
#define CP_COMMIT() asm volatile("cp.async.commit_group;" ::: "memory")
#define SW128(o) ((o) ^ ((((uint32_t)(o)) >> 3) & 0x70))

// ---------------- 1. gating ----------------
__global__ void gating_kernel(const float* __restrict__ x,
                              const float* __restrict__ noise,
                              const float* __restrict__ Wg, const float* __restrict__ bg,
                              const float* __restrict__ Wn, const float* __restrict__ bn)
{
    int warp = (blockIdx.x * blockDim.x + threadIdx.x) >> 5;
    int lane = threadIdx.x & 31;
    if (warp >= F_TOT) return;
    const float* xr = x + (size_t)warp * Dd;
    float ag[Ee], an[Ee];
#pragma unroll
    for (int e = 0; e < Ee; e++) { ag[e] = 0.f; an[e] = 0.f; }
    for (int d = lane; d < Dd; d += 32) {
        float xv = xr[d];
#pragma unroll
        for (int e = 0; e < Ee; e++) {
            ag[e] = fmaf(xv, Wg[d * Ee + e], ag[e]);
            an[e] = fmaf(xv, Wn[d * Ee + e], an[e]);
        }
    }
#pragma unroll
    for (int off = 16; off > 0; off >>= 1)
#pragma unroll
        for (int e = 0; e < Ee; e++) {
            ag[e] += __shfl_down_sync(0xffffffffu, ag[e], off);
            an[e] += __shfl_down_sync(0xffffffffu, an[e], off);
        }
    if (lane == 0) {
        float noisy[Ee];
#pragma unroll
        for (int e = 0; e < Ee; e++) {
            float l  = ag[e] + bg[e];
            float nl = an[e] + bn[e];
            float sp = fmaxf(nl, 0.f) + log1pf(expf(-fabsf(nl)));
            noisy[e] = l + noise[(size_t)warp * Ee + e] * sp;
        }
        int i0 = 0;
#pragma unroll
        for (int e = 1; e < Ee; e++) if (noisy[e] > noisy[i0]) i0 = e;
        int i1 = -1;
#pragma unroll
        for (int e = 0; e < Ee; e++) {
            if (e == i0) continue;
            if (i1 < 0 || noisy[e] > noisy[i1]) i1 = e;
        }
        float z = expf(noisy[i1] - noisy[i0]);
        float g0 = 1.f / (1.f + z);
        g_topi[warp * 2 + 0] = i0;
        g_topi[warp * 2 + 1] = i1;
        g_gate[warp * 2 + 0] = g0;
        g_gate[warp * 2 + 1] = z * g0;
    }
}

// ---------------- 2. per-expert token-order scan ----------------
__global__ void scan_kernel()
{
    const int e = blockIdx.x;
    const int tid = threadIdx.x;
    __shared__ int sdata[256];
    __shared__ int sbase;
    if (tid == 0) sbase = 0;
    __syncthreads();
    for (int start = 0; start < F_TOT; start += 256) {
        int t = start + tid;
        int i0 = g_topi[t * 2 + 0];
        int i1 = g_topi[t * 2 + 1];
        int m = (i0 == e || i1 == e) ? 1 : 0;
        sdata[tid] = m;
        __syncthreads();
#pragma unroll
        for (int off = 1; off < 256; off <<= 1) {
            int v = (tid >= off) ? sdata[tid - off] : 0;
            __syncthreads();
            sdata[tid] += v;
            __syncthreads();
        }
        int p = sbase + sdata[tid] - 1;
        if (m) {
            int k = (i0 == e) ? 0 : 1;
            if (p < CAP) { g_disp[e * CAP + p] = t; g_pos[t * 2 + k] = p; }
            else         { g_pos[t * 2 + k] = -1; }
        }
        __syncthreads();
        if (tid == 0) sbase += sdata[255];
        __syncthreads();
    }
    if (tid == 0) g_count[e] = min(sbase, CAP);
}

// ---------------- 3. gather + bf16 split ----------------
__global__ void gather_split_kernel(const float* __restrict__ x)
{
    int e = blockIdx.x / CAP;
    int c = blockIdx.x % CAP;
    size_t base = ((size_t)e * CAP + c) * Dd + threadIdx.x * 4;
    if (c < g_count[e]) {
        int t = g_disp[e * CAP + c];
        float4 v = ((const float4*)(x + (size_t)t * Dd))[threadIdx.x];
        float vv[4] = {v.x, v.y, v.z, v.w};
#pragma unroll
        for (int q = 0; q < 4; q += 2) {
            __nv_bfloat16 h0 = __float2bfloat16(vv[q]);
            __nv_bfloat16 h1 = __float2bfloat16(vv[q + 1]);
            __nv_bfloat16 l0 = __float2bfloat16(vv[q] - __bfloat162float(h0));
            __nv_bfloat16 l1 = __float2bfloat16(vv[q + 1] - __bfloat162float(h1));
            *(__nv_bfloat162*)(g_xin_h + base + q) = __halves2bfloat162(h0, h1);
            *(__nv_bfloat162*)(g_xin_l + base + q) = __halves2bfloat162(l0, l1);
        }
    } else {
        __nv_bfloat162 z = __halves2bfloat162(__float2bfloat16(0.f), __float2bfloat16(0.f));
#pragma unroll
        for (int q = 0; q < 4; q += 2) {
            *(__nv_bfloat162*)(g_xin_h + base + q) = z;
            *(__nv_bfloat162*)(g_xin_l + base + q) = z;
        }
    }
}

// ---------------- 4. weight transpose + split ----------------
__global__ void transpose_split_kernel(const float* __restrict__ W,
                                       __nv_bfloat16* __restrict__ Th,
                                       __nv_bfloat16* __restrict__ Tl,
                                       int R, int C)
{
    __shared__ float tile[32][33];
    int e = blockIdx.z;
    const float* We = W + (size_t)e * R * C;
    int c = blockIdx.x * 32 + threadIdx.x;
#pragma unroll
    for (int j = 0; j < 4; j++) {
        int r = blockIdx.y * 32 + threadIdx.y + j * 8;
        tile[threadIdx.y + j * 8][threadIdx.x] = We[(size_t)r * C + c];
    }
    __syncthreads();
    int r2 = blockIdx.y * 32 + threadIdx.x;
    size_t ebase = (size_t)e * C * R;
#pragma unroll
    for (int j = 0; j < 4; j++) {
        int c2 = blockIdx.x * 32 + threadIdx.y + j * 8;
        float v = tile[threadIdx.x][threadIdx.y + j * 8];
        __nv_bfloat16 h = __float2bfloat16(v);
        __nv_bfloat16 l = __float2bfloat16(v - __bfloat162float(h));
        Th[ebase + (size_t)c2 * R + r2] = h;
        Tl[ebase + (size_t)c2 * R + r2] = l;
    }
}

// ---------------- 5. GEMM: tile 128x256, BK=64, split-bf16 (hh+hl+lh) ----------------
// stage layout (96KB): Ah(16K) Al(16K) Bh(32K) Bl(32K); 2 stages at sb+1024.
__device__ __forceinline__ void stage_load(uint32_t stoff,
    const __nv_bfloat16* Ah, const __nv_bfloat16* Al,
    const __nv_bfloat16* Bh, const __nv_bfloat16* Bl,
    int m0, int n0, int K, int k0, int tid)
{
#pragma unroll
    for (int i = 0; i < 24; i++) {
        int c = i * 256 + tid;            // 0..6143 16B chunks
        const __nv_bfloat16* src;
        uint32_t dst;
        if (c < 2048) {                   // A region: Ah[0:1024), Al[1024:2048)
            int cc = c & 1023;
            int row = cc >> 3, kc = cc & 7;
            const __nv_bfloat16* T = (c < 1024) ? Ah : Al;
            src = T + (size_t)(m0 + row) * K + k0 + kc * 8;
            dst = stoff + (c < 1024 ? 0u : 16384u) + SW128(row * 128 + kc * 16);
        } else {                          // B region: Bh[0:2048), Bl[2048:4096)
            int c2 = c - 2048;
            int cc = c2 & 2047;
            int row = cc >> 3, kc = cc & 7;
            const __nv_bfloat16* T = (c2 < 2048) ? Bh : Bl;
            src = T + (size_t)(n0 + row) * K + k0 + kc * 8;
            dst = stoff + 32768u + (c2 < 2048 ? 0u : 32768u) + SW128(row * 128 + kc * 16);
        }
        asm volatile("cp.async.cg.shared.global [%0], [%1], 16;" :: "r"(dst), "l"(src));
    }
}

__global__ void __launch_bounds__(256, 1)
moe_gemm_kernel(const __nv_bfloat16* __restrict__ Ah, const __nv_bfloat16* __restrict__ Al,
                const __nv_bfloat16* __restrict__ Bh, const __nv_bfloat16* __restrict__ Bl,
                const float* __restrict__ bias,
                __nv_bfloat16* __restrict__ outH, __nv_bfloat16* __restrict__ outL,
                float* __restrict__ outF,
                int K, int Ntot, int mode)
{
    extern __shared__ __align__(1024) char smem[];
    int e = blockIdx.z;
    int m0 = blockIdx.y * 128;
    if (m0 >= g_count[e]) return;
    int n0 = blockIdx.x * 256;
    int tid = threadIdx.x;
    int wid = tid >> 5, lid = tid & 31;

    const __nv_bfloat16* eAh = Ah + (size_t)e * CAP * K;
    const __nv_bfloat16* eAl = Al + (size_t)e * CAP * K;
    const __nv_bfloat16* eBh = Bh + (size_t)e * Ntot * K;
    const __nv_bfloat16* eBl = Bl + (size_t)e * Ntot * K;
    const float* ebias = bias + (size_t)e * Ntot;

    uint32_t sb = smem_u32(smem);
    const int S = K >> 6;
    const uint32_t STG = 98304u;

    // prefetch 2 stages
    stage_load(sb + 1024, eAh, eAl, eBh, eBl, m0, n0, K, 0, tid);
    CP_COMMIT();
    stage_load(sb + 1024 + STG, eAh, eAl, eBh, eBl, m0, n0, K, 64, tid);
    CP_COMMIT();

#if HAS_TCGEN05
    // ================= tcgen05 path =================
    uint32_t mbar0 = sb + 16, mbar1 = sb + 24;
    if (tid == 0) {
        asm volatile("mbarrier.init.shared.b64 [%0], 1;" :: "r"(mbar0) : "memory");
        asm volatile("mbarrier.init.shared.b64 [%0], 1;" :: "r"(mbar1) : "memory");
    }
    if (wid == 0)
        asm volatile("tcgen05.alloc.cta_group::1.sync.aligned.shared::cta.b32 [%0], 256;"
                     :: "r"(sb) : "memory");
    __syncthreads();
    uint32_t tmem;
    asm volatile("ld.shared.b32 %0, [%1];" : "=r"(tmem) : "r"(sb));

    // M=128 (8<<24), N=256 (32<<17), bf16 (1<<7 | 1<<10), F32 accum (1<<4)
    const uint32_t IDESC = (8u << 24) | (32u << 17) | (1u << 10) | (1u << 7) | (1u << 4);
    int ph0 = 0, ph1 = 0;
    for (int s = 0; s < S; s++) {
        if (s < S - 1) asm volatile("cp.async.wait_group 1;" ::: "memory");
        else           asm volatile("cp.async.wait_group 0;" ::: "memory");
        asm volatile("fence.proxy.async.shared::cta;" ::: "memory");
        __syncthreads();
        uint32_t stoff = sb + 1024 + (uint32_t)(s & 1) * STG;
        uint32_t pred;
        asm volatile("{ .reg .pred p; elect.sync _|p, 0xFFFFFFFF; selp.b32 %0, 1, 0, p; }" : "=r"(pred));
        if (wid == 0 && pred) {
            uint64_t base = ((uint64_t)2 << 61) | ((uint64_t)1 << 46) | ((uint64_t)64 << 32) | ((uint64_t)1 << 16);
            uint64_t dAh = base | ((stoff >> 4) & 0x3FFF);
            uint64_t dAl = base | (((stoff + 16384u) >> 4) & 0x3FFF);
            uint64_t dBh = base | (((stoff + 32768u) >> 4) & 0x3FFF);
            uint64_t dBl = base | (((stoff + 65536u) >> 4) & 0x3FFF);
#pragma unroll
            for (int kc = 0; kc < 4; kc++) {
                uint32_t en = (s | kc) != 0;
                asm volatile("{ .reg .pred p; setp.ne.u32 p, %4, 0;\n\t"
                    "tcgen05.mma.cta_group::1.kind::f16 [%0], %1, %2, %3, {%5,%5,%5,%5}, p; }"
                    :: "r"(tmem), "l"(dAh + kc * 2), "l"(dBh + kc * 2), "r"(IDESC), "r"(en), "r"(0u) : "memory");
            }
#pragma unroll
            for (int kc = 0; kc < 4; kc++)
                asm volatile("{ .reg .pred p; setp.ne.u32 p, 1, 0;\n\t"
                    "tcgen05.mma.cta_group::1.kind::f16 [%0], %1, %2, %3, {%4,%4,%4,%4}, p; }"
                    :: "r"(tmem), "l"(dAh + kc * 2), "l"(dBl + kc * 2), "r"(IDESC), "r"(0u) : "memory");
#pragma unroll
            for (int kc = 0; kc < 4; kc++)
                asm volatile("{ .reg .pred p; setp.ne.u32 p, 1, 0;\n\t"
                    "tcgen05.mma.cta_group::1.kind::f16 [%0], %1, %2, %3, {%4,%4,%4,%4}, p; }"
                    :: "r"(tmem), "l"(dAl + kc * 2), "l"(dBh + kc * 2), "r"(IDESC), "r"(0u) : "memory");
            asm volatile("tcgen05.commit.cta_group::1.mbarrier::arrive::one.shared::cluster.b64 [%0];"
                         :: "r"((s & 1) ? mbar1 : mbar0) : "memory");
        }
        if (s + 2 < S) {
            uint32_t mb = (s & 1) ? mbar1 : mbar0;
            uint32_t pp = (s & 1) ? ph1 : ph0;
            asm volatile("{ .reg .pred P1;\n\t"
                "WL_%=:\n\t"
                "mbarrier.try_wait.parity.acquire.cta.shared::cta.b64 P1, [%0], %1, 0x989680;\n\t"
                "@P1 bra.uni WD_%=;\n\tbra.uni WL_%=;\n\tWD_%=:\n\t}"
                :: "r"(mb), "r"(pp) : "memory");
            if (s & 1) ph1 ^= 1; else ph0 ^= 1;
            stage_load(sb + 1024 + (uint32_t)(s & 1) * STG,
                       eAh, eAl, eBh, eBl, m0, n0, K, (s + 2) * 64, tid);
            CP_COMMIT();
        }
    }
    {
        uint32_t mb = ((S - 1) & 1) ? mbar1 : mbar0;
        uint32_t pp = ((S - 1) & 1) ? ph1 : ph0;
        asm volatile("{ .reg .pred P1;\n\t"
            "WL_%=:\n\t"
            "mbarrier.try_wait.parity.acquire.cta.shared::cta.b64 P1, [%0], %1, 0x989680;\n\t"
            "@P1 bra.uni WD_%=;\n\tbra.uni WL_%=;\n\tWD_%=:\n\t}"
            :: "r"(mb), "r"(pp) : "memory");
    }
    asm volatile("tcgen05.fence::after_thread_sync;" ::: "memory");

    // epilogue: both warpgroups. warp w -> rows (w&3)*32, cols (w>>2)*128 + ch*32
    {
        int rowgrp = wid & 3;
        int colhalf = wid >> 2;
        uint32_t woff = (uint32_t)rowgrp << 21;
        int m = m0 + rowgrp * 32 + lid;
#pragma unroll 1
        for (int ch = 0; ch < 4; ch++) {
            uint32_t r[32];
            asm volatile("tcgen05.ld.sync.aligned.32x32b.x32.b32 "
                "{%0, %1, %2, %3, %4, %5, %6, %7, "
                " %8, %9, %10, %11, %12, %13, %14, %15, "
                " %16, %17, %18, %19, %20, %21, %22, %23, "
                " %24, %25, %26, %27, %28, %29, %30, %31}, [%32];"
                : "=r"(r[0]), "=r"(r[1]), "=r"(r[2]), "=r"(r[3]),
                  "=r"(r[4]), "=r"(r[5]), "=r"(r[6]), "=r"(r[7]),
                  "=r"(r[8]), "=r"(r[9]), "=r"(r[10]), "=r"(r[11]),
                  "=r"(r[12]), "=r"(r[13]), "=r"(r[14]), "=r"(r[15]),
                  "=r"(r[16]), "=r"(r[17]), "=r"(r[18]), "=r"(r[19]),
                  "=r"(r[20]), "=r"(r[21]), "=r"(r[22]), "=r"(r[23]),
                  "=r"(r[24]), "=r"(r[25]), "=r"(r[26]), "=r"(r[27]),
                  "=r"(r[28]), "=r"(r[29]), "=r"(r[30]), "=r"(r[31])
                : "r"(tmem + woff + colhalf * 128 + ch * 32));
            asm volatile("tcgen05.wait::ld.sync.aligned;" ::: "memory");
            int nbase = n0 + colhalf * 128 + ch * 32;
            if (mode == 1) {
                __nv_bfloat16* ph_ = outH + ((size_t)e * CAP + m) * Ntot + nbase;
                __nv_bfloat16* pl_ = outL + ((size_t)e * CAP + m) * Ntot + nbase;
#pragma unroll
                for (int j = 0; j < 32; j += 2) {
                    float v0 = __uint_as_float(r[j])     + ebias[nbase + j];
                    float v1 = __uint_as_float(r[j + 1]) + ebias[nbase + j + 1];
                    v0 = 0.5f * v0 * (1.f + erff(v0 * 0.70710678118654752f));
                    v1 = 0.5f * v1 * (1.f + erff(v1 * 0.70710678118654752f));
                    __nv_bfloat16 h0 = __float2bfloat16(v0);
                    __nv_bfloat16 h1 = __float2bfloat16(v1);
                    __nv_bfloat16 l0 = __float2bfloat16(v0 - __bfloat162float(h0));
                    __nv_bfloat16 l1 = __float2bfloat16(v1 - __bfloat162float(h1));
                    *(__nv_bfloat162*)(ph_ + j) = __halves2bfloat162(h0, h1);
                    *(__nv_bfloat162*)(pl_ + j) = __halves2bfloat162(l0, l1);
                }
            } else {
                float* po = outF + ((size_t)e * CAP + m) * Ntot + nbase;
#pragma unroll
                for (int j = 0; j < 32; j += 4) {
                    float4 v;
                    v.x = __uint_as_float(r[j])     + ebias[nbase + j];
                    v.y = __uint_as_float(r[j + 1]) + ebias[nbase + j + 1];
                    v.z = __uint_as_float(r[j + 2]) + ebias[nbase + j + 2];
                    v.w = __uint_as_float(r[j + 3]) + ebias[nbase + j + 3];
                    *(float4*)(po + j) = v;
                }
            }
        }
    }
    __syncthreads();
    if (wid == 0) {
        asm volatile("tcgen05.relinquish_alloc_permit.cta_group::1.sync.aligned;");
        asm volatile("tcgen05.dealloc.cta_group::1.sync.aligned.b32 %0, 256;" :: "r"(tmem));
    }
#else
    // ================= mma.sync bf16 fallback (plain sm_103; compile-only safety net) =================
    #define LDSM_X4(r0_, r1_, r2_, r3_, addr_)                                   \
        asm volatile("ldmatrix.sync.aligned.m8n8.x4.shared.b16 {%0,%1,%2,%3}, [%4];" \
            : "=r"(r0_), "=r"(r1_), "=r"(r2_), "=r"(r3_) : "r"(addr_))
    #define MMA16816(d_, a_, b_)                                                 \
        asm volatile("mma.sync.aligned.m16n8k16.row.col.f32.bf16.bf16.f32 "      \
            "{%0,%1,%2,%3}, {%4,%5,%6,%7}, {%8,%9}, {%0,%1,%2,%3};"              \
            : "+f"((d_)[0]), "+f"((d_)[1]), "+f"((d_)[2]), "+f"((d_)[3])          \
            : "r"((a_)[0]), "r"((a_)[1]), "r"((a_)[2]), "r"((a_)[3]),             \
              "r"((b_)[0]), "r"((b_)[1]))

    int wm = wid & 3;       // M quadrant (32 rows)
    int wn = wid >> 2;      // N half (128 cols)
    float acc[2][16][4];
#pragma unroll
    for (int mi = 0; mi < 2; mi++)
#pragma unroll
        for (int nt = 0; nt < 16; nt++)
#pragma unroll
            for (int q = 0; q < 4; q++) acc[mi][nt][q] = 0.f;

    int ar  = wm * 32;
    int bnb = wn * 128;
    uint32_t a_lrow = (uint32_t)(lid & 15);
    uint32_t a_lk   = (uint32_t)((lid >> 4) * 16);

    for (int s = 0; s < S; s++) {
        if (s < S - 1) asm volatile("cp.async.wait_group 1;" ::: "memory");
        else           asm volatile("cp.async.wait_group 0;" ::: "memory");
        __syncthreads();
        uint32_t so = sb + 1024 + (uint32_t)(s & 1) * STG;
        uint32_t aoffH = so, aoffL = so + 16384u, boffH = so + 32768u, boffL = so + 65536u;
#pragma unroll
        for (int ks = 0; ks < 4; ks++) {
            uint32_t kb = (uint32_t)ks * 32u + a_lk;
            uint32_t ah[2][4], al[2][4], bh[16][2], bl[16][2];
#pragma unroll
            for (int mi = 0; mi < 2; mi++) {
                uint32_t off = SW128((ar + mi * 16 + a_lrow) * 128u + kb);
                LDSM_X4(ah[mi][0], ah[mi][1], ah[mi][2], ah[mi][3], aoffH + off);
                LDSM_X4(al[mi][0], al[mi][1], al[mi][2], al[mi][3], aoffL + off);
            }
#pragma unroll
            for (int p = 0; p < 8; p++) {
                uint32_t off = SW128((bnb + p * 16 + a_lrow) * 128u + kb);
                uint32_t r0, r1, r2, r3;
                LDSM_X4(r0, r1, r2, r3, boffH + off);
                bh[2*p][0] = r0; bh[2*p][1] = r2; bh[2*p+1][0] = r1; bh[2*p+1][1] = r3;
                LDSM_X4(r0, r1, r2, r3, boffL + off);
                bl[2*p][0] = r0; bl[2*p][1] = r2; bl[2*p+1][0] = r1; bl[2*p+1][1] = r3;
            }
#pragma unroll
            for (int mi = 0; mi < 2; mi++)
#pragma unroll
                for (int nt = 0; nt < 16; nt++) {
                    MMA16816(acc[mi][nt], ah[mi], bh[nt]);
                    MMA16816(acc[mi][nt], ah[mi], bl[nt]);
                    MMA16816(acc[mi][nt], al[mi], bh[nt]);
                }
        }
        __syncthreads();
        if (s + 2 < S) {
            stage_load(sb + 1024 + (uint32_t)(s & 1) * STG,
                       eAh, eAl, eBh, eBl, m0, n0, K, (s + 2) * 64, tid);
            CP_COMMIT();
        }
    }

#pragma unroll
    for (int mi = 0; mi < 2; mi++)
#pragma unroll
        for (int nt = 0; nt < 16; nt++) {
            int col = n0 + wn * 128 + nt * 8 + (lid & 3) * 2;
#pragma unroll
            for (int half = 0; half < 2; half++) {
                int row = m0 + wm * 32 + mi * 16 + (lid >> 2) + half * 8;
                float v0 = acc[mi][nt][half * 2 + 0] + ebias[col];
                float v1 = acc[mi][nt][half * 2 + 1] + ebias[col + 1];
                if (mode == 1) {
                    v0 = 0.5f * v0 * (1.f + erff(v0 * 0.70710678118654752f));
                    v1 = 0.5f * v1 * (1.f + erff(v1 * 0.70710678118654752f));
                    __nv_bfloat16 h0 = __float2bfloat16(v0);
                    __nv_bfloat16 h1 = __float2bfloat16(v1);
                    __nv_bfloat16 l0 = __float2bfloat16(v0 - __bfloat162float(h0));
                    __nv_bfloat16 l1 = __float2bfloat16(v1 - __bfloat162float(h1));
                    size_t o = ((size_t)e * CAP + row) * Ntot + col;
                    *(__nv_bfloat162*)(outH + o) = __halves2bfloat162(h0, h1);
                    *(__nv_bfloat162*)(outL + o) = __halves2bfloat162(l0, l1);
                } else {
                    float2 v; v.x = v0; v.y = v1;
                    *(float2*)(outF + ((size_t)e * CAP + row) * Ntot + col) = v;
                }
            }
        }
#endif
}

// ---------------- 6. deterministic combine ----------------
__global__ void combine_kernel(float* __restrict__ out)
{
    int t = blockIdx.x;
    int i0 = g_topi[t * 2 + 0], i1 = g_topi[t * 2 + 1];
    int p0 = g_pos [t * 2 + 0], p1 = g_pos [t * 2 + 1];
    float gv0 = g_gate[t * 2 + 0], gv1 = g_gate[t * 2 + 1];
    float4 acc = make_float4(0.f, 0.f, 0.f, 0.f);
    int d4 = threadIdx.x;
    if (p0 >= 0) {
        float4 a = ((const float4*)(g_out2 + ((size_t)i0 * CAP + p0) * Dd))[d4];
        acc.x += gv0 * a.x; acc.y += gv0 * a.y; acc.z += gv0 * a.z; acc.w += gv0 * a.w;
    }
    if (p1 >= 0) {
        float4 b = ((const float4*)(g_out2 + ((size_t)i1 * CAP + p1) * Dd))[d4];
        acc.x += gv1 * b.x; acc.y += gv1 * b.y; acc.z += gv1 * b.z; acc.w += gv1 * b.w;
    }
    ((float4*)(out + (size_t)t * Dd))[d4] = acc;
}

// ---------------- launch ----------------
extern "C" void kernel_launch(void* const* d_in, const int* in_sizes, int n_in,
                              void* d_out, int out_size)
{
    const float* x     = (const float*)d_in[0];
    const float* noise = (const float*)d_in[1];
    const float* Wg    = (const float*)d_in[2];
    const float* bg    = (const float*)d_in[3];
    const float* Wn    = (const float*)d_in[4];
    const float* bn    = (const float*)d_in[5];
    const float* W1    = (const float*)d_in[6];
    const float* b1    = (const float*)d_in[7];
    const float* W2    = (const float*)d_in[8];
    const float* b2    = (const float*)d_in[9];
    float* out = (float*)d_out;

    cudaFuncSetAttribute(moe_gemm_kernel,
                         cudaFuncAttributeMaxDynamicSharedMemorySize, 197632);

    __nv_bfloat16 *xin_h, *xin_l, *w1t_h, *w1t_l, *w2t_h, *w2t_l, *h_h, *h_l;
    float* out2;
    cudaGetSymbolAddress((void**)&xin_h, g_xin_h);
    cudaGetSymbolAddress((void**)&xin_l, g_xin_l);
    cudaGetSymbolAddress((void**)&w1t_h, g_w1t_h);
    cudaGetSymbolAddress((void**)&w1t_l, g_w1t_l);
    cudaGetSymbolAddress((void**)&w2t_h, g_w2t_h);
    cudaGetSymbolAddress((void**)&w2t_l, g_w2t_l);
    cudaGetSymbolAddress((void**)&h_h, g_h_h);
    cudaGetSymbolAddress((void**)&h_l, g_h_l);
    cudaGetSymbolAddress((void**)&out2, g_out2);

    gating_kernel<<<F_TOT / 8, 256>>>(x, noise, Wg, bg, Wn, bn);
    scan_kernel<<<Ee, 256>>>();
    gather_split_kernel<<<Ee * CAP, 256>>>(x);
    transpose_split_kernel<<<dim3(FFf / 32, Dd / 32, Ee), dim3(32, 8)>>>(W1, w1t_h, w1t_l, Dd, FFf);
    transpose_split_kernel<<<dim3(Dd / 32, FFf / 32, Ee), dim3(32, 8)>>>(W2, w2t_h, w2t_l, FFf, Dd);

    // GEMM1: M=CAP, N=FF, K=D; bias b1; GELU; split-bf16 output
    moe_gemm_kernel<<<dim3(FFf / 256, CAP / 128, Ee), 256, 197632>>>(
        xin_h, xin_l, w1t_h, w1t_l, b1, h_h, h_l, nullptr, Dd, FFf, 1);
    // GEMM2: M=CAP, N=D, K=FF; bias b2; fp32 output
    moe_gemm_kernel<<<dim3(Dd / 256, CAP / 128, Ee), 256, 197632>>>(
        h_h, h_l, w2t_h, w2t_l, b2, nullptr, nullptr, out2, FFf, Dd, 0);

    combine_kernel<<<F_TOT, 256>>>(out);
}